// round 11
// baseline (speedup 1.0000x reference)
#include <cuda_runtime.h>
#include <cuda_bf16.h>
#include <cstdint>

// EnVAE: B=8192, OBS=4096, LAT=64, NG=4, GS=1024, H=128
namespace {
constexpr int BATCH = 8192;
constexpr int OBS   = 4096;
constexpr int LATD  = 64;
constexpr int NGRP  = 4;
constexpr int GSZ   = 1024;
constexpr int HID   = 128;
constexpr int ENC1_SMEM = 98304;   // 2 stages x 48KB (A 16K, B 32K); epilogue h 64K + w2e 32K
constexpr int DEC2_SMEM = 98304;   // 2 stages x 48KB
}

// ------------------------- scratch (__device__ globals) ---------------------
__device__ float g_ml[BATCH * NGRP * HID];
__device__ __align__(16) __nv_bfloat16 g_hd_hi[BATCH * NGRP * LATD];
__device__ __align__(16) __nv_bfloat16 g_hd_lo[BATCH * NGRP * LATD];
__device__ __align__(16) __nv_bfloat16 g_w1t_hi[NGRP * GSZ * HID];   // [g][n<128][k<1024]
__device__ __align__(16) __nv_bfloat16 g_w1t_lo[NGRP * GSZ * HID];
__device__ __align__(16) __nv_bfloat16 g_w2e_hi[NGRP * HID * HID];   // [g][n<128][k<128]
__device__ __align__(16) __nv_bfloat16 g_w2e_lo[NGRP * HID * HID];
__device__ __align__(16) __nv_bfloat16 g_w2t_hi[NGRP * GSZ * LATD];  // [g][o<1024][m<64]
__device__ __align__(16) __nv_bfloat16 g_w2t_lo[NGRP * GSZ * LATD];

__constant__ int c_masks[15] = {1,2,4,8, 3,5,9,6,10,12, 7,11,13,14, 15};

// ------------------------- helpers (base sm_100 only!) ----------------------
__device__ __forceinline__ uint32_t smem_u32(const void* p) {
    uint32_t a;
    asm("{ .reg .u64 t; cvta.to.shared.u64 t, %1; cvt.u32.u64 %0, t; }" : "=r"(a) : "l"(p));
    return a;
}
__device__ __forceinline__ uint32_t sw64(uint32_t off)  { return off ^ ((off >> 3) & 0x30); }
__device__ __forceinline__ uint32_t sw128(uint32_t off) { return off ^ ((off >> 3) & 0x70); }
__device__ __forceinline__ uint32_t pack2(__nv_bfloat16 a, __nv_bfloat16 b) {
    return (uint32_t)__bfloat16_as_ushort(a) | ((uint32_t)__bfloat16_as_ushort(b) << 16);
}
__device__ __forceinline__ void split_bf16(float x, __nv_bfloat16& h, __nv_bfloat16& l) {
    h = __float2bfloat16(x);
    l = __float2bfloat16(x - __bfloat162float(h));
}
__device__ __forceinline__ void cp16(uint32_t dst, const void* src) {
    asm volatile("cp.async.cg.shared.global [%0], [%1], 16;" :: "r"(dst), "l"(src));
}
#define CP_COMMIT asm volatile("cp.async.commit_group;")
#define CP_WAIT0  asm volatile("cp.async.wait_group 0;" ::: "memory")

__device__ __forceinline__ void ldsm4(uint32_t (&d)[4], uint32_t addr) {
    asm volatile("ldmatrix.sync.aligned.m8n8.x4.shared.b16 {%0,%1,%2,%3}, [%4];"
        : "=r"(d[0]), "=r"(d[1]), "=r"(d[2]), "=r"(d[3]) : "r"(addr));
}
__device__ __forceinline__ void mma16816(float (&c)[4], const uint32_t (&a)[4],
                                         const uint32_t (&b)[2]) {
    asm volatile("mma.sync.aligned.m16n8k16.row.col.f32.bf16.bf16.f32 "
        "{%0,%1,%2,%3},{%4,%5,%6,%7},{%8,%9},{%0,%1,%2,%3};"
        : "+f"(c[0]), "+f"(c[1]), "+f"(c[2]), "+f"(c[3])
        : "r"(a[0]), "r"(a[1]), "r"(a[2]), "r"(a[3]), "r"(b[0]), "r"(b[1]));
}

// ------------------------- weight prep: tiled transpose + split -------------
__global__ void prep_wt(const float* __restrict__ src,
                        __nv_bfloat16* __restrict__ hi, __nv_bfloat16* __restrict__ lo,
                        int K, int N)
{
    __shared__ float s[32][33];
    const int kt = blockIdx.x * 32, nt = blockIdx.y * 32, g = blockIdx.z;
    const int tx = threadIdx.x, ty = threadIdx.y;
    const float* sp = src + (size_t)g * K * N;
#pragma unroll
    for (int i = 0; i < 4; i++)
        s[ty + 8 * i][tx] = sp[(size_t)(kt + ty + 8 * i) * N + nt + tx];
    __syncthreads();
    __nv_bfloat16* hp = hi + (size_t)g * K * N;
    __nv_bfloat16* lp = lo + (size_t)g * K * N;
#pragma unroll
    for (int i = 0; i < 4; i++) {
        float v = s[tx][ty + 8 * i];
        __nv_bfloat16 h, l2;
        split_bf16(v, h, l2);
        size_t o = (size_t)(nt + ty + 8 * i) * K + kt + tx;
        hp[o] = h; lp[o] = l2;
    }
}

// ------------------------- enc1+enc2 fused, 2-group CTA, 2 CTAs/SM ----------
// CTA: 64 rows x 256 cols (groups pair*2, pair*2+1). 8 warps = 2(M) x 4(N),
// warp tile 32x64 (identical micro-structure to the proven R8 kernel).
// X loaded as float4 (all 4 groups of one k), 2 of 4 components used;
// sibling pair-CTA (adjacent blockIdx.x) shares the sectors via L2.
// Stage (48KB): A at (lg*2+pl)*4096 (64 rows x 32k, 64B rows sw64);
//               B hi at +16384, lo at +32768 (256 rows [lg*128+n] x 64B).
// Epilogue: h planes lg*32768 + kb*16384 + pl*8192 (64 rows x 64k, 128B sw128)
//           at [0,64K); w2e chunk at 65536 (hi) / 81920 (lo).
__global__ __launch_bounds__(256, 2) void enc1_mma(
    const float* __restrict__ X, const float* __restrict__ bias1,
    const float* __restrict__ bias2)
{
    extern __shared__ char smem[];
    const uint32_t sb = smem_u32(smem);
    const int tid = threadIdx.x, l = tid & 31, w = tid >> 5;
    const int wm = w >> 2, wn = w & 3;
    const int gl = wn >> 1, nh = wn & 1;
    const int pair = blockIdx.x;                // 0,1: groups {0,1} / {2,3}
    const int row0 = blockIdx.y * 64;
    const int xr = tid >> 2, xq = tid & 3;      // A loader: row 0..63, k-octet 0..3

    float acc[2][8][4];
#pragma unroll
    for (int i = 0; i < 2; i++)
#pragma unroll
        for (int j = 0; j < 8; j++)
#pragma unroll
            for (int q = 0; q < 4; q++) acc[i][j][q] = 0.f;

    auto fillB = [&](int s, int k0) {
        uint32_t st = sb + (uint32_t)s * 49152 + 16384;
#pragma unroll
        for (int i = 0; i < 8; i++) {
            int c = tid + i * 256;              // 0..2047
            int q2 = c & 3;
            int rowid = c >> 2;                 // 0..511
            int pl = rowid >> 8;
            int rl = rowid & 255;               // lg*128+n
            uint32_t d = sw64((uint32_t)(rl * 64 + q2 * 16));
            const char* src = pl ? (const char*)g_w1t_lo : (const char*)g_w1t_hi;
            cp16(st + (uint32_t)pl * 16384 + d,
                 src + ((size_t)(pair * 256 + rl) * GSZ + k0) * 2 + q2 * 16);
        }
    };
    // half = 0/1 covers k = k0 + xq*8 + half*4 .. +3 (4 float4s = 4 k)
    auto ldgA4 = [&](float4 (&x)[4], int k0, int half) {
        const float4* xp = (const float4*)(X + (size_t)(row0 + xr) * OBS
                                           + 4 * (k0 + xq * 8 + half * 4));
#pragma unroll
        for (int j = 0; j < 4; j++) x[j] = xp[j];
    };
    auto stsA4 = [&](const float4 (&x)[4], int s, int half) {
        const float* xa = (const float*)x;
        uint32_t base = (uint32_t)s * 49152;
        uint32_t o = sw64((uint32_t)(xr * 64 + xq * 16)) + (uint32_t)half * 8;
#pragma unroll
        for (int lg2 = 0; lg2 < 2; lg2++) {
            int comp = pair * 2 + lg2;          // group component within float4
            __nv_bfloat16 h0,l0,h1,l1,h2,l2,h3,l3;
            split_bf16(xa[0 + comp],  h0, l0);
            split_bf16(xa[4 + comp],  h1, l1);
            split_bf16(xa[8 + comp],  h2, l2);
            split_bf16(xa[12 + comp], h3, l3);
            uint2 hv = make_uint2(pack2(h0, h1), pack2(h2, h3));
            uint2 lv = make_uint2(pack2(l0, l1), pack2(l2, l3));
            *(uint2*)(smem + base + (lg2 * 2 + 0) * 4096 + o) = hv;
            *(uint2*)(smem + base + (lg2 * 2 + 1) * 4096 + o) = lv;
        }
    };

    // one k16 sub-step of the 3-pass split MMA (mainloop)
    auto compute_ks = [&](int s, int ks) {
        uint32_t S = sb + (uint32_t)s * 49152;
        uint32_t Ah = S + (uint32_t)gl * 8192;            // lo at +4096
        uint32_t Bb = S + 16384;                          // lo at +16384
        const int arow = wm * 32 + (l & 15);
        const int brow0 = gl * 128 + nh * 64;
        const int ak = (ks * 16 + (l >> 4) * 8) * 2;
        const int bk = (ks * 16 + ((l >> 3) & 1) * 8) * 2;
        uint32_t ahi[2][4], alo[2][4], b[8][2];
        ldsm4(ahi[0], Ah + sw64((uint32_t)(arow * 64 + ak)));
        ldsm4(ahi[1], Ah + sw64((uint32_t)((arow + 16) * 64 + ak)));
        ldsm4(alo[0], Ah + 4096 + sw64((uint32_t)(arow * 64 + ak)));
        ldsm4(alo[1], Ah + 4096 + sw64((uint32_t)((arow + 16) * 64 + ak)));
#pragma unroll
        for (int p = 0; p < 4; p++) {
            int br = brow0 + p * 16 + (l & 7) + ((l >> 4) << 3);
            uint32_t t[4];
            ldsm4(t, Bb + sw64((uint32_t)(br * 64 + bk)));
            b[2*p][0]=t[0]; b[2*p][1]=t[1]; b[2*p+1][0]=t[2]; b[2*p+1][1]=t[3];
        }
#pragma unroll
        for (int mt = 0; mt < 2; mt++)
#pragma unroll
            for (int nt = 0; nt < 8; nt++) mma16816(acc[mt][nt], ahi[mt], b[nt]);
#pragma unroll
        for (int mt = 0; mt < 2; mt++)
#pragma unroll
            for (int nt = 0; nt < 8; nt++) mma16816(acc[mt][nt], alo[mt], b[nt]);
#pragma unroll
        for (int p = 0; p < 4; p++) {
            int br = brow0 + p * 16 + (l & 7) + ((l >> 4) << 3);
            uint32_t t[4];
            ldsm4(t, Bb + 16384 + sw64((uint32_t)(br * 64 + bk)));
            b[2*p][0]=t[0]; b[2*p][1]=t[1]; b[2*p+1][0]=t[2]; b[2*p+1][1]=t[3];
        }
#pragma unroll
        for (int mt = 0; mt < 2; mt++)
#pragma unroll
            for (int nt = 0; nt < 8; nt++) mma16816(acc[mt][nt], ahi[mt], b[nt]);
    };

    fillB(0, 0); CP_COMMIT;
    {
        float4 x0[4];
        ldgA4(x0, 0, 0); stsA4(x0, 0, 0);
        ldgA4(x0, 0, 1); stsA4(x0, 0, 1);
    }
    CP_WAIT0; __syncthreads();

    for (int c = 0; c < 32; c++) {
        int s = c & 1;
        bool pre = c < 31;
        float4 xa[4];
        if (pre) { fillB(s ^ 1, (c + 1) * 32); CP_COMMIT; ldgA4(xa, (c + 1) * 32, 0); }
        compute_ks(s, 0);
        float4 xb[4];
        if (pre) { stsA4(xa, s ^ 1, 0); ldgA4(xb, (c + 1) * 32, 1); }
        compute_ks(s, 1);
        if (pre) { stsA4(xb, s ^ 1, 1); CP_WAIT0; }
        __syncthreads();
    }

    // ---------------- fused epilogue 1: h -> smem (enc2 A operand) ----------
#pragma unroll
    for (int mt = 0; mt < 2; mt++)
#pragma unroll
        for (int nt = 0; nt < 8; nt++) {
            int col = (pair * 2 + gl) * HID + nh * 64 + nt * 8 + (l & 3) * 2;
            float b0 = bias1[col], b1 = bias1[col + 1];
            int rloc = wm * 32 + mt * 16 + (l >> 2);
            float v0 = fmaxf(acc[mt][nt][0] + b0, 0.f);
            float v1 = fmaxf(acc[mt][nt][1] + b1, 0.f);
            float v2 = fmaxf(acc[mt][nt][2] + b0, 0.f);
            float v3 = fmaxf(acc[mt][nt][3] + b1, 0.f);
            uint32_t koff = (uint32_t)(nt * 8 + (l & 3) * 2) * 2;  // bytes in 128B row
            uint32_t hb = (uint32_t)gl * 32768 + (uint32_t)nh * 16384;
            __nv_bfloat16 h0, l0, h1, l1;
            split_bf16(v0, h0, l0); split_bf16(v1, h1, l1);
            *(uint32_t*)(smem + hb +        sw128((uint32_t)(rloc * 128) + koff)) = pack2(h0, h1);
            *(uint32_t*)(smem + hb + 8192 + sw128((uint32_t)(rloc * 128) + koff)) = pack2(l0, l1);
            split_bf16(v2, h0, l0); split_bf16(v3, h1, l1);
            *(uint32_t*)(smem + hb +        sw128((uint32_t)((rloc + 8) * 128) + koff)) = pack2(h0, h1);
            *(uint32_t*)(smem + hb + 8192 + sw128((uint32_t)((rloc + 8) * 128) + koff)) = pack2(l0, l1);
        }
    __syncthreads();

    // ---------------- fused enc2: ml = h @ w2e + b2 --------------------------
#pragma unroll
    for (int i = 0; i < 2; i++)
#pragma unroll
        for (int j = 0; j < 8; j++)
#pragma unroll
            for (int q = 0; q < 4; q++) acc[i][j][q] = 0.f;

    auto fillB2 = [&](int kc) {
        uint32_t st = sb + 65536;
#pragma unroll
        for (int i = 0; i < 8; i++) {
            int c = tid + i * 256;              // 0..2047
            int q2 = c & 3;
            int rowid = c >> 2;                 // 0..511
            int pl = rowid >> 8;
            int rl = rowid & 255;               // lg*128+n
            const char* src = pl ? (const char*)g_w2e_lo : (const char*)g_w2e_hi;
            cp16(st + (uint32_t)pl * 16384 + sw64((uint32_t)(rl * 64 + q2 * 16)),
                 src + ((size_t)(pair * 256 + rl) * HID + kc * 32) * 2 + q2 * 16);
        }
    };

    for (int kc = 0; kc < 4; kc++) {
        fillB2(kc); CP_COMMIT; CP_WAIT0;
        __syncthreads();
        uint32_t Ab = sb + (uint32_t)gl * 32768 + (uint32_t)(kc >> 1) * 16384;
        uint32_t Bb = sb + 65536;               // lo at +16384
        const int arow = wm * 32 + (l & 15);
        const int brow0 = gl * 128 + nh * 64;
#pragma unroll
        for (int ks2 = 0; ks2 < 2; ks2++) {
            const int ak = ((kc & 1) * 32 + ks2 * 16 + (l >> 4) * 8) * 2;
            const int bk = (ks2 * 16 + ((l >> 3) & 1) * 8) * 2;
            uint32_t ahi[2][4], alo[2][4], b[8][2];
            ldsm4(ahi[0], Ab + sw128((uint32_t)(arow * 128 + ak)));
            ldsm4(ahi[1], Ab + sw128((uint32_t)((arow + 16) * 128 + ak)));
            ldsm4(alo[0], Ab + 8192 + sw128((uint32_t)(arow * 128 + ak)));
            ldsm4(alo[1], Ab + 8192 + sw128((uint32_t)((arow + 16) * 128 + ak)));
#pragma unroll
            for (int p = 0; p < 4; p++) {
                int br = brow0 + p * 16 + (l & 7) + ((l >> 4) << 3);
                uint32_t t[4];
                ldsm4(t, Bb + sw64((uint32_t)(br * 64 + bk)));
                b[2*p][0]=t[0]; b[2*p][1]=t[1]; b[2*p+1][0]=t[2]; b[2*p+1][1]=t[3];
            }
#pragma unroll
            for (int mt = 0; mt < 2; mt++)
#pragma unroll
                for (int nt = 0; nt < 8; nt++) mma16816(acc[mt][nt], ahi[mt], b[nt]);
#pragma unroll
            for (int mt = 0; mt < 2; mt++)
#pragma unroll
                for (int nt = 0; nt < 8; nt++) mma16816(acc[mt][nt], alo[mt], b[nt]);
#pragma unroll
            for (int p = 0; p < 4; p++) {
                int br = brow0 + p * 16 + (l & 7) + ((l >> 4) << 3);
                uint32_t t[4];
                ldsm4(t, Bb + 16384 + sw64((uint32_t)(br * 64 + bk)));
                b[2*p][0]=t[0]; b[2*p][1]=t[1]; b[2*p+1][0]=t[2]; b[2*p+1][1]=t[3];
            }
#pragma unroll
            for (int mt = 0; mt < 2; mt++)
#pragma unroll
                for (int nt = 0; nt < 8; nt++) mma16816(acc[mt][nt], ahi[mt], b[nt]);
        }
        __syncthreads();
    }

    // ---------------- epilogue 2: write g_ml ---------------------------------
#pragma unroll
    for (int mt = 0; mt < 2; mt++)
#pragma unroll
        for (int nt = 0; nt < 8; nt++) {
            int col = (pair * 2 + gl) * HID + nh * 64 + nt * 8 + (l & 3) * 2;
            float b0 = bias2[col], b1 = bias2[col + 1];
            int r1 = row0 + wm * 32 + mt * 16 + (l >> 2);
            size_t i1 = (size_t)r1 * (NGRP * HID) + col;
            float2 p1 = { acc[mt][nt][0] + b0, acc[mt][nt][1] + b1 };
            *(float2*)(g_ml + i1) = p1;
            float2 p2 = { acc[mt][nt][2] + b0, acc[mt][nt][3] + b1 };
            *(float2*)(g_ml + i1 + (size_t)8 * (NGRP * HID)) = p2;
        }
}

// ------------------------- dec1 (fused kz + dec1, emits bf16 hi/lo) ---------
__global__ __launch_bounds__(256) void kdec1(const float* __restrict__ w1,
                                             const float* __restrict__ b1,
                                             const float* __restrict__ eps,
                                             const int* __restrict__ sidx)
{
    const int row0 = blockIdx.x * 32;
    const int tid  = threadIdx.x;
    __shared__ float zs[32][64];
#pragma unroll
    for (int p = 0; p < 8; p++) {
        int t = tid + p * 256;
        int r = t >> 6, ll = t & 63;
        int b = row0 + r;
        int m = c_masks[sidx[b]];
        const float* pm = g_ml + (size_t)b * (NGRP * HID) + ll;
        float tau = 1.f, num = 0.f;
#pragma unroll
        for (int g = 0; g < 4; g++) {
            if ((m >> g) & 1) {
                float mean = pm[g * HID];
                float lv   = pm[g * HID + 64];
                float tg   = expf(-lv);
                tau += tg;
                num += tg * mean;
            }
        }
        zs[r][ll] = num / tau + eps[(size_t)b * LATD + ll] * rsqrtf(tau);
    }
    const int g = tid >> 6, m = tid & 63;
    float w[64];
#pragma unroll
    for (int l = 0; l < 64; l++) w[l] = w1[g * 4096 + l * 64 + m];
    const float bv = b1[g * 64 + m];
    __syncthreads();
#pragma unroll 4
    for (int r = 0; r < 32; r++) {
        float acc = bv;
#pragma unroll
        for (int l = 0; l < 64; l++) acc += zs[r][l] * w[l];
        float v = fmaxf(acc, 0.f);
        __nv_bfloat16 h, lo;
        split_bf16(v, h, lo);
        int idx = (row0 + r) * (NGRP * LATD) + g * 64 + m;
        g_hd_hi[idx] = h;
        g_hd_lo[idx] = lo;
    }
}

// ------------------------- dec2: mma.sync, 4-group fused float4 scatter -----
__global__ __launch_bounds__(256, 1) void dec2_mma(
    const float* __restrict__ b2, float* __restrict__ recon)
{
    extern __shared__ char smem[];
    const uint32_t sb = smem_u32(smem);
    const int tid = threadIdx.x, l = tid & 31, w = tid >> 5;
    const int wm = w >> 1, wn = w & 1;
    const int o0 = blockIdx.x * 64, row0 = blockIdx.y * 128;

    float acc[4][2][4][4];
#pragma unroll
    for (int g = 0; g < 4; g++)
#pragma unroll
        for (int i = 0; i < 2; i++)
#pragma unroll
            for (int j = 0; j < 4; j++)
#pragma unroll
                for (int q = 0; q < 4; q++) acc[g][i][j][q] = 0.f;

    auto fill = [&](int s, int g) {
        uint32_t st = sb + (uint32_t)s * 49152;
#pragma unroll
        for (int p = 0; p < 4; p++) {
            int c = tid + p * 256;
            int row = c >> 3, q = c & 7;
            uint32_t d = sw128(row * 128 + q * 16);
            size_t off = ((size_t)(row0 + row) * (NGRP * LATD) + g * LATD) * 2 + q * 16;
            cp16(st + d,         (const char*)g_hd_hi + off);
            cp16(st + 16384 + d, (const char*)g_hd_lo + off);
        }
#pragma unroll
        for (int p = 0; p < 2; p++) {
            int c = tid + p * 256;
            int row = c >> 3, q = c & 7;
            uint32_t d = sw128(row * 128 + q * 16);
            size_t off = (((size_t)g * GSZ + (o0 + row)) * LATD) * 2 + q * 16;
            cp16(st + 32768 + d, (const char*)g_w2t_hi + off);
            cp16(st + 40960 + d, (const char*)g_w2t_lo + off);
        }
    };

    fill(0, 0); CP_COMMIT; CP_WAIT0; __syncthreads();

    const int arow = wm * 32 + (l & 15);
    const int brow = wn * 32 + (l & 7) + ((l >> 4) << 3);
    for (int g = 0; g < 4; g++) {
        int s = g & 1;
        if (g < 3) { fill(s ^ 1, g + 1); CP_COMMIT; }
        uint32_t st = sb + (uint32_t)s * 49152;
#pragma unroll
        for (int ks = 0; ks < 4; ks++) {
            const int ak = (ks * 16 + (l >> 4) * 8) * 2;
            const int bk = (ks * 16 + ((l >> 3) & 1) * 8) * 2;
            uint32_t ao[2], bo[2];
            ao[0] = sw128(arow * 128 + ak); ao[1] = sw128((arow + 16) * 128 + ak);
            bo[0] = sw128(brow * 128 + bk); bo[1] = sw128((brow + 16) * 128 + bk);
            uint32_t a[2][4], b[4][2], bl[4][2];
#pragma unroll
            for (int p = 0; p < 2; p++) {
                uint32_t t[4];
                ldsm4(t, st + 32768 + bo[p]);
                b[2*p][0]=t[0]; b[2*p][1]=t[1]; b[2*p+1][0]=t[2]; b[2*p+1][1]=t[3];
                ldsm4(t, st + 40960 + bo[p]);
                bl[2*p][0]=t[0]; bl[2*p][1]=t[1]; bl[2*p+1][0]=t[2]; bl[2*p+1][1]=t[3];
            }
            ldsm4(a[0], st + ao[0]); ldsm4(a[1], st + ao[1]);       // Ahi
#pragma unroll
            for (int mt = 0; mt < 2; mt++)
#pragma unroll
                for (int nt = 0; nt < 4; nt++) mma16816(acc[g][mt][nt], a[mt], b[nt]);
#pragma unroll
            for (int mt = 0; mt < 2; mt++)
#pragma unroll
                for (int nt = 0; nt < 4; nt++) mma16816(acc[g][mt][nt], a[mt], bl[nt]);
            ldsm4(a[0], st + 16384 + ao[0]); ldsm4(a[1], st + 16384 + ao[1]);  // Alo
#pragma unroll
            for (int mt = 0; mt < 2; mt++)
#pragma unroll
                for (int nt = 0; nt < 4; nt++) mma16816(acc[g][mt][nt], a[mt], b[nt]);
        }
        if (g < 3) CP_WAIT0;
        __syncthreads();
    }

#pragma unroll
    for (int mt = 0; mt < 2; mt++)
#pragma unroll
        for (int nt = 0; nt < 4; nt++) {
            int oo = o0 + wn * 32 + nt * 8 + (l & 3) * 2;
            int r1 = row0 + wm * 32 + mt * 16 + (l >> 2);
            float b20 = b2[0*GSZ+oo], b21 = b2[1*GSZ+oo], b22 = b2[2*GSZ+oo], b23 = b2[3*GSZ+oo];
            float c20 = b2[0*GSZ+oo+1], c21 = b2[1*GSZ+oo+1], c22 = b2[2*GSZ+oo+1], c23 = b2[3*GSZ+oo+1];
            float4 v;
            v.x = acc[0][mt][nt][0]+b20; v.y = acc[1][mt][nt][0]+b21;
            v.z = acc[2][mt][nt][0]+b22; v.w = acc[3][mt][nt][0]+b23;
            *(float4*)(recon + (size_t)r1 * OBS + 4 * oo) = v;
            v.x = acc[0][mt][nt][1]+c20; v.y = acc[1][mt][nt][1]+c21;
            v.z = acc[2][mt][nt][1]+c22; v.w = acc[3][mt][nt][1]+c23;
            *(float4*)(recon + (size_t)r1 * OBS + 4 * (oo + 1)) = v;
            int r2 = r1 + 8;
            v.x = acc[0][mt][nt][2]+b20; v.y = acc[1][mt][nt][2]+b21;
            v.z = acc[2][mt][nt][2]+b22; v.w = acc[3][mt][nt][2]+b23;
            *(float4*)(recon + (size_t)r2 * OBS + 4 * oo) = v;
            v.x = acc[0][mt][nt][3]+c20; v.y = acc[1][mt][nt][3]+c21;
            v.z = acc[2][mt][nt][3]+c22; v.w = acc[3][mt][nt][3]+c23;
            *(float4*)(recon + (size_t)r2 * OBS + 4 * (oo + 1)) = v;
        }
}

// ---------------------------------------------------------------------------
extern "C" void kernel_launch(void* const* d_in, const int* in_sizes, int n_in,
                              void* d_out, int out_size)
{
    const float* X   = (const float*)d_in[0];
    const float* eps = (const float*)d_in[1];
    const int*   sidx= (const int*)  d_in[2];
    const float* ew1 = (const float*)d_in[3];
    const float* eb1 = (const float*)d_in[4];
    const float* ew2 = (const float*)d_in[5];
    const float* eb2 = (const float*)d_in[6];
    const float* dw1 = (const float*)d_in[7];
    const float* db1 = (const float*)d_in[8];
    const float* dw2 = (const float*)d_in[9];
    const float* db2 = (const float*)d_in[10];
    float* recon = (float*)d_out;

    __nv_bfloat16 *w1h, *w1l, *w2eh, *w2el, *w2th, *w2tl;
    cudaGetSymbolAddress((void**)&w1h,  g_w1t_hi);
    cudaGetSymbolAddress((void**)&w1l,  g_w1t_lo);
    cudaGetSymbolAddress((void**)&w2eh, g_w2e_hi);
    cudaGetSymbolAddress((void**)&w2el, g_w2e_lo);
    cudaGetSymbolAddress((void**)&w2th, g_w2t_hi);
    cudaGetSymbolAddress((void**)&w2tl, g_w2t_lo);

    cudaFuncSetAttribute(enc1_mma, cudaFuncAttributeMaxDynamicSharedMemorySize, ENC1_SMEM);
    cudaFuncSetAttribute(dec2_mma, cudaFuncAttributeMaxDynamicSharedMemorySize, DEC2_SMEM);

    prep_wt<<<dim3(GSZ/32, HID/32, NGRP), dim3(32, 8)>>>(ew1, w1h, w1l, GSZ, HID);
    prep_wt<<<dim3(HID/32, HID/32, NGRP), dim3(32, 8)>>>(ew2, w2eh, w2el, HID, HID);
    prep_wt<<<dim3(LATD/32, GSZ/32, NGRP), dim3(32, 8)>>>(dw2, w2th, w2tl, LATD, GSZ);

    enc1_mma<<<dim3(2, BATCH / 64), 256, ENC1_SMEM>>>(X, eb1, eb2);
    kdec1<<<BATCH / 32, 256>>>(dw1, db1, eps, sidx);
    dec2_mma<<<dim3(GSZ / 64, BATCH / 128), 256, DEC2_SMEM>>>(db2, recon);
}

// round 12
// speedup vs baseline: 1.3163x; 1.3163x over previous
#include <cuda_runtime.h>
#include <cuda_bf16.h>
#include <cstdint>

// EnVAE: B=8192, OBS=4096, LAT=64, NG=4, GS=1024, H=128
namespace {
constexpr int BATCH = 8192;
constexpr int OBS   = 4096;
constexpr int LATD  = 64;
constexpr int NGRP  = 4;
constexpr int GSZ   = 1024;
constexpr int HID   = 128;
constexpr int ENC1_SMEM = 196608;  // mainloop: 2 stages x 96KB; epilogue: h 128KB + w2e chunk 64KB
constexpr int DEC2_SMEM = 65536;   // 2 stages x 32KB (A 16K: 2pl x 8K; B 16K: 2pl x 8K)
}

// ------------------------- scratch (__device__ globals) ---------------------
__device__ float g_ml[BATCH * NGRP * HID];
__device__ __align__(16) __nv_bfloat16 g_hd_hi[BATCH * NGRP * LATD];
__device__ __align__(16) __nv_bfloat16 g_hd_lo[BATCH * NGRP * LATD];
__device__ __align__(16) __nv_bfloat16 g_w1t_hi[NGRP * GSZ * HID];   // [g][n<128][k<1024]
__device__ __align__(16) __nv_bfloat16 g_w1t_lo[NGRP * GSZ * HID];
__device__ __align__(16) __nv_bfloat16 g_w2e_hi[NGRP * HID * HID];   // [g][n<128][k<128]
__device__ __align__(16) __nv_bfloat16 g_w2e_lo[NGRP * HID * HID];
__device__ __align__(16) __nv_bfloat16 g_w2t_hi[NGRP * GSZ * LATD];  // [g][o<1024][m<64]
__device__ __align__(16) __nv_bfloat16 g_w2t_lo[NGRP * GSZ * LATD];

__constant__ int c_masks[15] = {1,2,4,8, 3,5,9,6,10,12, 7,11,13,14, 15};

// ------------------------- helpers (base sm_100 only!) ----------------------
__device__ __forceinline__ uint32_t smem_u32(const void* p) {
    uint32_t a;
    asm("{ .reg .u64 t; cvta.to.shared.u64 t, %1; cvt.u32.u64 %0, t; }" : "=r"(a) : "l"(p));
    return a;
}
__device__ __forceinline__ uint32_t sw64(uint32_t off)  { return off ^ ((off >> 3) & 0x30); }
__device__ __forceinline__ uint32_t sw128(uint32_t off) { return off ^ ((off >> 3) & 0x70); }
__device__ __forceinline__ uint32_t pack2(__nv_bfloat16 a, __nv_bfloat16 b) {
    return (uint32_t)__bfloat16_as_ushort(a) | ((uint32_t)__bfloat16_as_ushort(b) << 16);
}
__device__ __forceinline__ void split_bf16(float x, __nv_bfloat16& h, __nv_bfloat16& l) {
    h = __float2bfloat16(x);
    l = __float2bfloat16(x - __bfloat162float(h));
}
__device__ __forceinline__ void cp16(uint32_t dst, const void* src) {
    asm volatile("cp.async.cg.shared.global [%0], [%1], 16;" :: "r"(dst), "l"(src));
}
#define CP_COMMIT asm volatile("cp.async.commit_group;")
#define CP_WAIT0  asm volatile("cp.async.wait_group 0;" ::: "memory")

__device__ __forceinline__ void ldsm4(uint32_t (&d)[4], uint32_t addr) {
    asm volatile("ldmatrix.sync.aligned.m8n8.x4.shared.b16 {%0,%1,%2,%3}, [%4];"
        : "=r"(d[0]), "=r"(d[1]), "=r"(d[2]), "=r"(d[3]) : "r"(addr));
}
__device__ __forceinline__ void mma16816(float (&c)[4], const uint32_t (&a)[4],
                                         const uint32_t (&b)[2]) {
    asm volatile("mma.sync.aligned.m16n8k16.row.col.f32.bf16.bf16.f32 "
        "{%0,%1,%2,%3},{%4,%5,%6,%7},{%8,%9},{%0,%1,%2,%3};"
        : "+f"(c[0]), "+f"(c[1]), "+f"(c[2]), "+f"(c[3])
        : "r"(a[0]), "r"(a[1]), "r"(a[2]), "r"(a[3]), "r"(b[0]), "r"(b[1]));
}

// ------------------------- weight prep: tiled transpose + split -------------
__global__ void prep_wt(const float* __restrict__ src,
                        __nv_bfloat16* __restrict__ hi, __nv_bfloat16* __restrict__ lo,
                        int K, int N)
{
    __shared__ float s[32][33];
    const int kt = blockIdx.x * 32, nt = blockIdx.y * 32, g = blockIdx.z;
    const int tx = threadIdx.x, ty = threadIdx.y;
    const float* sp = src + (size_t)g * K * N;
#pragma unroll
    for (int i = 0; i < 4; i++)
        s[ty + 8 * i][tx] = sp[(size_t)(kt + ty + 8 * i) * N + nt + tx];
    __syncthreads();
    __nv_bfloat16* hp = hi + (size_t)g * K * N;
    __nv_bfloat16* lp = lo + (size_t)g * K * N;
#pragma unroll
    for (int i = 0; i < 4; i++) {
        float v = s[tx][ty + 8 * i];
        __nv_bfloat16 h, l2;
        split_bf16(v, h, l2);
        size_t o = (size_t)(nt + ty + 8 * i) * K + kt + tx;
        hp[o] = h; lp[o] = l2;
    }
}

// ------------------------- enc1+enc2 fused mma.sync GEMM (R10, proven) ------
__global__ __launch_bounds__(512, 1) void enc1_mma(
    const float* __restrict__ X, const float* __restrict__ bias1,
    const float* __restrict__ bias2)
{
    extern __shared__ char smem[];
    const uint32_t sb = smem_u32(smem);
    const int tid = threadIdx.x, l = tid & 31, w = tid >> 5;
    const int wm = w >> 3, wn = w & 7;
    const int g = wn >> 1, nh = wn & 1;
    const int row0 = blockIdx.x * 64;
    const int xr = tid >> 3, xq = tid & 7;     // A loader: row 0..63, k-quarter 0..7

    float acc[2][8][4];
#pragma unroll
    for (int i = 0; i < 2; i++)
#pragma unroll
        for (int j = 0; j < 8; j++)
#pragma unroll
            for (int q = 0; q < 4; q++) acc[i][j][q] = 0.f;

    auto fillB = [&](int s, int k0) {
        uint32_t st = sb + (uint32_t)s * 98304 + 32768;
#pragma unroll
        for (int i = 0; i < 8; i++) {
            int c = tid + i * 512;             // 0..4095
            int q2 = c & 3;
            int rowid = c >> 2;                // 0..1023
            int pl = rowid >> 9;
            int rl = rowid & 511;              // g*128+n
            uint32_t d = sw64((uint32_t)(rl * 64 + q2 * 16));
            const char* src = pl ? (const char*)g_w1t_lo : (const char*)g_w1t_hi;
            cp16(st + (uint32_t)pl * 32768 + d, src + ((size_t)rl * GSZ + k0) * 2 + q2 * 16);
        }
    };
    auto ldgA = [&](float4 (&x)[4], int k0) {
        const float4* xp = (const float4*)(X + (size_t)(row0 + xr) * OBS + 4 * k0 + 16 * xq);
#pragma unroll
        for (int j = 0; j < 4; j++) x[j] = xp[j];
    };
    auto stsA = [&](const float4 (&x)[4], int s) {
        const float* xa = (const float*)x;
        uint32_t base = (uint32_t)s * 98304;
        uint32_t o16 = sw64((uint32_t)(xr * 64 + (xq >> 1) * 16)) + (xq & 1) * 8;
#pragma unroll
        for (int gg = 0; gg < 4; gg++) {
            __nv_bfloat16 h0,l0,h1,l1,h2,l2,h3,l3;
            split_bf16(xa[0 + gg], h0, l0);
            split_bf16(xa[4 + gg], h1, l1);
            split_bf16(xa[8 + gg], h2, l2);
            split_bf16(xa[12 + gg], h3, l3);
            uint2 hv = make_uint2(pack2(h0, h1), pack2(h2, h3));
            uint2 lv = make_uint2(pack2(l0, l1), pack2(l2, l3));
            *(uint2*)(smem + base + (gg * 2 + 0) * 4096 + o16) = hv;
            *(uint2*)(smem + base + (gg * 2 + 1) * 4096 + o16) = lv;
        }
    };

    auto compute_ks = [&](int s, int ks) {
        uint32_t S = sb + (uint32_t)s * 98304;
        uint32_t Ah = S + (uint32_t)(g * 2) * 4096;       // lo at +4096
        uint32_t Bb = S + 32768;                          // lo at +32768
        const int arow = wm * 32 + (l & 15);
        const int brow0 = g * 128 + nh * 64;
        const int ak = (ks * 16 + (l >> 4) * 8) * 2;
        const int bk = (ks * 16 + ((l >> 3) & 1) * 8) * 2;
        uint32_t ahi[2][4], alo[2][4], b[8][2];
        ldsm4(ahi[0], Ah + sw64((uint32_t)(arow * 64 + ak)));
        ldsm4(ahi[1], Ah + sw64((uint32_t)((arow + 16) * 64 + ak)));
        ldsm4(alo[0], Ah + 4096 + sw64((uint32_t)(arow * 64 + ak)));
        ldsm4(alo[1], Ah + 4096 + sw64((uint32_t)((arow + 16) * 64 + ak)));
#pragma unroll
        for (int p = 0; p < 4; p++) {
            int br = brow0 + p * 16 + (l & 7) + ((l >> 4) << 3);
            uint32_t t[4];
            ldsm4(t, Bb + sw64((uint32_t)(br * 64 + bk)));
            b[2*p][0]=t[0]; b[2*p][1]=t[1]; b[2*p+1][0]=t[2]; b[2*p+1][1]=t[3];
        }
#pragma unroll
        for (int mt = 0; mt < 2; mt++)
#pragma unroll
            for (int nt = 0; nt < 8; nt++) mma16816(acc[mt][nt], ahi[mt], b[nt]);
#pragma unroll
        for (int mt = 0; mt < 2; mt++)
#pragma unroll
            for (int nt = 0; nt < 8; nt++) mma16816(acc[mt][nt], alo[mt], b[nt]);
#pragma unroll
        for (int p = 0; p < 4; p++) {
            int br = brow0 + p * 16 + (l & 7) + ((l >> 4) << 3);
            uint32_t t[4];
            ldsm4(t, Bb + 32768 + sw64((uint32_t)(br * 64 + bk)));
            b[2*p][0]=t[0]; b[2*p][1]=t[1]; b[2*p+1][0]=t[2]; b[2*p+1][1]=t[3];
        }
#pragma unroll
        for (int mt = 0; mt < 2; mt++)
#pragma unroll
            for (int nt = 0; nt < 8; nt++) mma16816(acc[mt][nt], ahi[mt], b[nt]);
    };

    fillB(0, 0); CP_COMMIT;
    { float4 x0[4]; ldgA(x0, 0); stsA(x0, 0); }
    CP_WAIT0; __syncthreads();

    for (int c = 0; c < 32; c++) {
        int s = c & 1;
        float4 xn[4];
        bool pre = c < 31;
        if (pre) { fillB(s ^ 1, (c + 1) * 32); CP_COMMIT; ldgA(xn, (c + 1) * 32); }
        compute_ks(s, 0);
        if (pre) stsA(xn, s ^ 1);
        compute_ks(s, 1);
        if (pre) CP_WAIT0;
        __syncthreads();
    }

    // ---------------- fused epilogue 1: h -> smem (enc2 A operand) ----------
#pragma unroll
    for (int mt = 0; mt < 2; mt++)
#pragma unroll
        for (int nt = 0; nt < 8; nt++) {
            int col = g * 128 + nh * 64 + nt * 8 + (l & 3) * 2;
            float b0 = bias1[col], b1 = bias1[col + 1];
            int rloc = wm * 32 + mt * 16 + (l >> 2);
            float v0 = fmaxf(acc[mt][nt][0] + b0, 0.f);
            float v1 = fmaxf(acc[mt][nt][1] + b1, 0.f);
            float v2 = fmaxf(acc[mt][nt][2] + b0, 0.f);
            float v3 = fmaxf(acc[mt][nt][3] + b1, 0.f);
            uint32_t koff = (uint32_t)(nt * 8 + (l & 3) * 2) * 2;  // bytes in 128B row
            uint32_t hb = (uint32_t)g * 32768 + (uint32_t)nh * 16384;
            __nv_bfloat16 h0, l0, h1, l1;
            split_bf16(v0, h0, l0); split_bf16(v1, h1, l1);
            *(uint32_t*)(smem + hb +        sw128((uint32_t)(rloc * 128) + koff)) = pack2(h0, h1);
            *(uint32_t*)(smem + hb + 8192 + sw128((uint32_t)(rloc * 128) + koff)) = pack2(l0, l1);
            split_bf16(v2, h0, l0); split_bf16(v3, h1, l1);
            *(uint32_t*)(smem + hb +        sw128((uint32_t)((rloc + 8) * 128) + koff)) = pack2(h0, h1);
            *(uint32_t*)(smem + hb + 8192 + sw128((uint32_t)((rloc + 8) * 128) + koff)) = pack2(l0, l1);
        }
    __syncthreads();

    // ---------------- fused enc2: ml = h @ w2e + b2 --------------------------
#pragma unroll
    for (int i = 0; i < 2; i++)
#pragma unroll
        for (int j = 0; j < 8; j++)
#pragma unroll
            for (int q = 0; q < 4; q++) acc[i][j][q] = 0.f;

    auto fillB2 = [&](int kc) {
        uint32_t st = sb + 131072;
#pragma unroll
        for (int i = 0; i < 8; i++) {
            int c = tid + i * 512;             // 0..4095
            int q2 = c & 3;
            int rowid = c >> 2;                // 0..1023
            int pl = rowid >> 9;
            int rl = rowid & 511;              // g*128+n
            const char* src = pl ? (const char*)g_w2e_lo : (const char*)g_w2e_hi;
            cp16(st + (uint32_t)pl * 32768 + sw64((uint32_t)(rl * 64 + q2 * 16)),
                 src + ((size_t)rl * HID + kc * 32) * 2 + q2 * 16);
        }
    };

    for (int kc = 0; kc < 4; kc++) {
        fillB2(kc); CP_COMMIT; CP_WAIT0;
        __syncthreads();
        uint32_t Ab = sb + (uint32_t)g * 32768 + (uint32_t)(kc >> 1) * 16384;
        uint32_t Bb = sb + 131072;                 // lo at +32768
        const int arow = wm * 32 + (l & 15);
        const int brow0 = g * 128 + nh * 64;
#pragma unroll
        for (int ks2 = 0; ks2 < 2; ks2++) {
            const int ak = ((kc & 1) * 32 + ks2 * 16 + (l >> 4) * 8) * 2;
            const int bk = (ks2 * 16 + ((l >> 3) & 1) * 8) * 2;
            uint32_t ahi[2][4], alo[2][4], b[8][2];
            ldsm4(ahi[0], Ab + sw128((uint32_t)(arow * 128 + ak)));
            ldsm4(ahi[1], Ab + sw128((uint32_t)((arow + 16) * 128 + ak)));
            ldsm4(alo[0], Ab + 8192 + sw128((uint32_t)(arow * 128 + ak)));
            ldsm4(alo[1], Ab + 8192 + sw128((uint32_t)((arow + 16) * 128 + ak)));
#pragma unroll
            for (int p = 0; p < 4; p++) {
                int br = brow0 + p * 16 + (l & 7) + ((l >> 4) << 3);
                uint32_t t[4];
                ldsm4(t, Bb + sw64((uint32_t)(br * 64 + bk)));
                b[2*p][0]=t[0]; b[2*p][1]=t[1]; b[2*p+1][0]=t[2]; b[2*p+1][1]=t[3];
            }
#pragma unroll
            for (int mt = 0; mt < 2; mt++)
#pragma unroll
                for (int nt = 0; nt < 8; nt++) mma16816(acc[mt][nt], ahi[mt], b[nt]);
#pragma unroll
            for (int mt = 0; mt < 2; mt++)
#pragma unroll
                for (int nt = 0; nt < 8; nt++) mma16816(acc[mt][nt], alo[mt], b[nt]);
#pragma unroll
            for (int p = 0; p < 4; p++) {
                int br = brow0 + p * 16 + (l & 7) + ((l >> 4) << 3);
                uint32_t t[4];
                ldsm4(t, Bb + 32768 + sw64((uint32_t)(br * 64 + bk)));
                b[2*p][0]=t[0]; b[2*p][1]=t[1]; b[2*p+1][0]=t[2]; b[2*p+1][1]=t[3];
            }
#pragma unroll
            for (int mt = 0; mt < 2; mt++)
#pragma unroll
                for (int nt = 0; nt < 8; nt++) mma16816(acc[mt][nt], ahi[mt], b[nt]);
        }
        __syncthreads();
    }

    // ---------------- epilogue 2: write g_ml ---------------------------------
#pragma unroll
    for (int mt = 0; mt < 2; mt++)
#pragma unroll
        for (int nt = 0; nt < 8; nt++) {
            int col = g * 128 + nh * 64 + nt * 8 + (l & 3) * 2;
            float b0 = bias2[col], b1 = bias2[col + 1];
            int r1 = row0 + wm * 32 + mt * 16 + (l >> 2);
            size_t i1 = (size_t)r1 * (NGRP * HID) + col;
            float2 p1 = { acc[mt][nt][0] + b0, acc[mt][nt][1] + b1 };
            *(float2*)(g_ml + i1) = p1;
            float2 p2 = { acc[mt][nt][2] + b0, acc[mt][nt][3] + b1 };
            *(float2*)(g_ml + i1 + (size_t)8 * (NGRP * HID)) = p2;
        }
}

// ------------------------- dec1 (fused kz + dec1, emits bf16 hi/lo) ---------
__global__ __launch_bounds__(256) void kdec1(const float* __restrict__ w1,
                                             const float* __restrict__ b1,
                                             const float* __restrict__ eps,
                                             const int* __restrict__ sidx)
{
    const int row0 = blockIdx.x * 32;
    const int tid  = threadIdx.x;
    __shared__ float zs[32][64];
#pragma unroll
    for (int p = 0; p < 8; p++) {
        int t = tid + p * 256;
        int r = t >> 6, ll = t & 63;
        int b = row0 + r;
        int m = c_masks[sidx[b]];
        const float* pm = g_ml + (size_t)b * (NGRP * HID) + ll;
        float tau = 1.f, num = 0.f;
#pragma unroll
        for (int g = 0; g < 4; g++) {
            if ((m >> g) & 1) {
                float mean = pm[g * HID];
                float lv   = pm[g * HID + 64];
                float tg   = expf(-lv);
                tau += tg;
                num += tg * mean;
            }
        }
        zs[r][ll] = num / tau + eps[(size_t)b * LATD + ll] * rsqrtf(tau);
    }
    const int g = tid >> 6, m = tid & 63;
    float w[64];
#pragma unroll
    for (int l = 0; l < 64; l++) w[l] = w1[g * 4096 + l * 64 + m];
    const float bv = b1[g * 64 + m];
    __syncthreads();
#pragma unroll 4
    for (int r = 0; r < 32; r++) {
        float acc = bv;
#pragma unroll
        for (int l = 0; l < 64; l++) acc += zs[r][l] * w[l];
        float v = fmaxf(acc, 0.f);
        __nv_bfloat16 h, lo;
        split_bf16(v, h, lo);
        int idx = (row0 + r) * (NGRP * LATD) + g * 64 + m;
        g_hd_hi[idx] = h;
        g_hd_lo[idx] = lo;
    }
}

// ------------------------- dec2: 64-row tiles, 2 CTAs/SM --------------------
// Tile: 64 rows x 64 o, all 4 groups. 8 warps = 4(M: 16 rows) x 2(N: 32 o).
// acc = 64 floats/thread -> ~110 regs -> 2 CTAs/SM. Stage 32KB (A 16K, B 16K).
__global__ __launch_bounds__(256, 2) void dec2_mma(
    const float* __restrict__ b2, float* __restrict__ recon)
{
    extern __shared__ char smem[];
    const uint32_t sb = smem_u32(smem);
    const int tid = threadIdx.x, l = tid & 31, w = tid >> 5;
    const int wm = w >> 1, wn = w & 1;
    const int o0 = blockIdx.x * 64, row0 = blockIdx.y * 64;

    float acc[4][4][4];   // [g][nt][q]
#pragma unroll
    for (int g = 0; g < 4; g++)
#pragma unroll
        for (int j = 0; j < 4; j++)
#pragma unroll
            for (int q = 0; q < 4; q++) acc[g][j][q] = 0.f;

    // Stage s (32KB): Ahi +0 (64 rows x 64m, 128B rows sw128), Alo +8192,
    //                 Bhi +16384 (64 o x 64m), Blo +24576.
    auto fill = [&](int s, int g) {
        uint32_t st = sb + (uint32_t)s * 32768;
#pragma unroll
        for (int p = 0; p < 4; p++) {
            int c = tid + p * 256;             // 0..1023
            int pl = c >> 9;
            int rq = c & 511;
            int row = rq >> 3, q = rq & 7;
            uint32_t d = (uint32_t)pl * 8192 + sw128((uint32_t)(row * 128 + q * 16));
            size_t aoff = ((size_t)(row0 + row) * (NGRP * LATD) + g * LATD) * 2 + q * 16;
            cp16(st + d, (pl ? (const char*)g_hd_lo : (const char*)g_hd_hi) + aoff);
            size_t boff = (((size_t)g * GSZ + (o0 + row)) * LATD) * 2 + q * 16;
            cp16(st + 16384 + d, (pl ? (const char*)g_w2t_lo : (const char*)g_w2t_hi) + boff);
        }
    };

    fill(0, 0); CP_COMMIT; CP_WAIT0; __syncthreads();

    const int arow = wm * 16 + (l & 15);
    for (int g = 0; g < 4; g++) {
        int s = g & 1;
        if (g < 3) { fill(s ^ 1, g + 1); CP_COMMIT; }
        uint32_t st = sb + (uint32_t)s * 32768;
#pragma unroll
        for (int ks = 0; ks < 4; ks++) {
            const int ak = (ks * 16 + (l >> 4) * 8) * 2;
            const int bk = (ks * 16 + ((l >> 3) & 1) * 8) * 2;
            uint32_t ao = sw128((uint32_t)(arow * 128 + ak));
            uint32_t bo[2];
#pragma unroll
            for (int p = 0; p < 2; p++) {
                int br = wn * 32 + p * 16 + (l & 7) + ((l >> 4) << 3);
                bo[p] = sw128((uint32_t)(br * 128 + bk));
            }
            uint32_t ahi[4], alo[4], b[4][2], bl[4][2];
            ldsm4(ahi, st + ao);
            ldsm4(alo, st + 8192 + ao);
#pragma unroll
            for (int p = 0; p < 2; p++) {
                uint32_t t[4];
                ldsm4(t, st + 16384 + bo[p]);
                b[2*p][0]=t[0]; b[2*p][1]=t[1]; b[2*p+1][0]=t[2]; b[2*p+1][1]=t[3];
                ldsm4(t, st + 24576 + bo[p]);
                bl[2*p][0]=t[0]; bl[2*p][1]=t[1]; bl[2*p+1][0]=t[2]; bl[2*p+1][1]=t[3];
            }
#pragma unroll
            for (int nt = 0; nt < 4; nt++) mma16816(acc[g][nt], ahi, b[nt]);
#pragma unroll
            for (int nt = 0; nt < 4; nt++) mma16816(acc[g][nt], ahi, bl[nt]);
#pragma unroll
            for (int nt = 0; nt < 4; nt++) mma16816(acc[g][nt], alo, b[nt]);
        }
        if (g < 3) CP_WAIT0;
        __syncthreads();
    }

#pragma unroll
    for (int nt = 0; nt < 4; nt++) {
        int oo = o0 + wn * 32 + nt * 8 + (l & 3) * 2;
        int r1 = row0 + wm * 16 + (l >> 2);
        float b20 = b2[0*GSZ+oo], b21 = b2[1*GSZ+oo], b22 = b2[2*GSZ+oo], b23 = b2[3*GSZ+oo];
        float c20 = b2[0*GSZ+oo+1], c21 = b2[1*GSZ+oo+1], c22 = b2[2*GSZ+oo+1], c23 = b2[3*GSZ+oo+1];
        float4 v;
        v.x = acc[0][nt][0]+b20; v.y = acc[1][nt][0]+b21;
        v.z = acc[2][nt][0]+b22; v.w = acc[3][nt][0]+b23;
        *(float4*)(recon + (size_t)r1 * OBS + 4 * oo) = v;
        v.x = acc[0][nt][1]+c20; v.y = acc[1][nt][1]+c21;
        v.z = acc[2][nt][1]+c22; v.w = acc[3][nt][1]+c23;
        *(float4*)(recon + (size_t)r1 * OBS + 4 * (oo + 1)) = v;
        int r2 = r1 + 8;
        v.x = acc[0][nt][2]+b20; v.y = acc[1][nt][2]+b21;
        v.z = acc[2][nt][2]+b22; v.w = acc[3][nt][2]+b23;
        *(float4*)(recon + (size_t)r2 * OBS + 4 * oo) = v;
        v.x = acc[0][nt][3]+c20; v.y = acc[1][nt][3]+c21;
        v.z = acc[2][nt][3]+c22; v.w = acc[3][nt][3]+c23;
        *(float4*)(recon + (size_t)r2 * OBS + 4 * (oo + 1)) = v;
    }
}

// ---------------------------------------------------------------------------
extern "C" void kernel_launch(void* const* d_in, const int* in_sizes, int n_in,
                              void* d_out, int out_size)
{
    const float* X   = (const float*)d_in[0];
    const float* eps = (const float*)d_in[1];
    const int*   sidx= (const int*)  d_in[2];
    const float* ew1 = (const float*)d_in[3];
    const float* eb1 = (const float*)d_in[4];
    const float* ew2 = (const float*)d_in[5];
    const float* eb2 = (const float*)d_in[6];
    const float* dw1 = (const float*)d_in[7];
    const float* db1 = (const float*)d_in[8];
    const float* dw2 = (const float*)d_in[9];
    const float* db2 = (const float*)d_in[10];
    float* recon = (float*)d_out;

    __nv_bfloat16 *w1h, *w1l, *w2eh, *w2el, *w2th, *w2tl;
    cudaGetSymbolAddress((void**)&w1h,  g_w1t_hi);
    cudaGetSymbolAddress((void**)&w1l,  g_w1t_lo);
    cudaGetSymbolAddress((void**)&w2eh, g_w2e_hi);
    cudaGetSymbolAddress((void**)&w2el, g_w2e_lo);
    cudaGetSymbolAddress((void**)&w2th, g_w2t_hi);
    cudaGetSymbolAddress((void**)&w2tl, g_w2t_lo);

    cudaFuncSetAttribute(enc1_mma, cudaFuncAttributeMaxDynamicSharedMemorySize, ENC1_SMEM);
    cudaFuncSetAttribute(dec2_mma, cudaFuncAttributeMaxDynamicSharedMemorySize, DEC2_SMEM);

    prep_wt<<<dim3(GSZ/32, HID/32, NGRP), dim3(32, 8)>>>(ew1, w1h, w1l, GSZ, HID);
    prep_wt<<<dim3(HID/32, HID/32, NGRP), dim3(32, 8)>>>(ew2, w2eh, w2el, HID, HID);
    prep_wt<<<dim3(LATD/32, GSZ/32, NGRP), dim3(32, 8)>>>(dw2, w2th, w2tl, LATD, GSZ);

    enc1_mma<<<BATCH / 64, 512, ENC1_SMEM>>>(X, eb1, eb2);
    kdec1<<<BATCH / 32, 256>>>(dw1, db1, eps, sidx);
    dec2_mma<<<dim3(GSZ / 64, BATCH / 64), 256, DEC2_SMEM>>>(db2, recon);
}